// round 2
// baseline (speedup 1.0000x reference)
#include <cuda_runtime.h>
#include <stdint.h>
#include <math.h>

#define T_ROWS 65536
#define CD 128
#define HD 64
#define KSH 512
#define KCO 16
#define RPB 16
#define NBLK (T_ROWS / RPB)

#define LOSS_OFF 8388608ul
#define PS_OFF   8388609ul
#define PC_OFF   8388610ul
#define IDX_OFF  8388611ul
#define US_OFF   8454147ul
#define UC_OFF   8454659ul

__device__ float  g_ww_s[KSH];
__device__ float  g_ww_c[KCO];
__device__ int    g_usage_s[KSH];
__device__ int    g_usage_c[KCO];
__device__ int    g_vcount;
__device__ double g_loss_part[NBLK];

// ---------------- threefry2x32 (JAX) ----------------
__device__ __forceinline__ uint32_t rotl32(uint32_t x, int d) {
    return (x << d) | (x >> (32 - d));
}
__device__ __forceinline__ void tf_r(uint32_t& x0, uint32_t& x1, int r) {
    x0 += x1; x1 = rotl32(x1, r); x1 ^= x0;
}
__device__ __forceinline__ uint2 threefry2x32(uint32_t k0, uint32_t k1,
                                              uint32_t x0, uint32_t x1) {
    uint32_t k2 = k0 ^ k1 ^ 0x1BD11BDAu;
    x0 += k0; x1 += k1;
    tf_r(x0,x1,13); tf_r(x0,x1,15); tf_r(x0,x1,26); tf_r(x0,x1,6);
    x0 += k1; x1 += k2 + 1u;
    tf_r(x0,x1,17); tf_r(x0,x1,29); tf_r(x0,x1,16); tf_r(x0,x1,24);
    x0 += k2; x1 += k0 + 2u;
    tf_r(x0,x1,13); tf_r(x0,x1,15); tf_r(x0,x1,26); tf_r(x0,x1,6);
    x0 += k0; x1 += k1 + 3u;
    tf_r(x0,x1,17); tf_r(x0,x1,29); tf_r(x0,x1,16); tf_r(x0,x1,24);
    x0 += k1; x1 += k2 + 4u;
    tf_r(x0,x1,13); tf_r(x0,x1,15); tf_r(x0,x1,26); tf_r(x0,x1,6);
    x0 += k2; x1 += k0 + 5u;
    return make_uint2(x0, x1);
}

// Partitionable threefry 32-bit draw at flat index idx: bits = out.x ^ out.y
// gumbel = -log(-log(max(tiny, u + tiny))),  u = bitcast((bits>>9)|0x3f800000)-1
__device__ __forceinline__ float gumbel_at(uint32_t k0, uint32_t k1,
                                           unsigned long long idx) {
    uint2 r = threefry2x32(k0, k1, (uint32_t)(idx >> 32), (uint32_t)idx);
    uint32_t bits = r.x ^ r.y;
    const float TINY = 1.17549435e-38f;
    float f = __uint_as_float(0x3F800000u | (bits >> 9)) - 1.0f;
    float u = fmaxf(TINY, __fadd_rn(f, TINY));
    return -logf(-logf(u));
}

// ---------------- kernel 0: code norms + zero accumulators ----------------
__global__ void k_init(const float* __restrict__ ws, const float* __restrict__ wc) {
    int t = threadIdx.x;
    if (t < KSH) {
        float s = 0.f;
        #pragma unroll
        for (int j = 0; j < HD; j++) {
            float v = ws[t * HD + j];
            s = __fadd_rn(s, __fmul_rn(v, v));
        }
        g_ww_s[t] = s;
        g_usage_s[t] = 0;
    }
    if (t < KCO) {
        float s = 0.f;
        #pragma unroll
        for (int j = 0; j < HD; j++) {
            float v = wc[t * HD + j];
            s = __fadd_rn(s, __fmul_rn(v, v));
        }
        g_ww_c[t] = s;
        g_usage_c[t] = 0;
    }
    if (t == 0) g_vcount = 0;
}

// ---------------- kernel 1: main (one warp per row) ----------------
__global__ __launch_bounds__(512) void k_main(const float* __restrict__ x,
                                              const float* __restrict__ ws,
                                              const float* __restrict__ wc,
                                              float* __restrict__ out) {
    __shared__ __align__(16) float sx[RPB][CD];
    __shared__ __align__(16) float wt[64][68];
    __shared__ __align__(16) float wcs[KCO][68];
    __shared__ uint32_t skey[4];
    __shared__ float s_loss[RPB];

    int tid = threadIdx.x, lane = tid & 31, wrp = tid >> 5;
    size_t row0 = (size_t)blockIdx.x * RPB;

    if (tid == 0) {
        // jax.random.split(jax.random.key(42)) — foldlike: child i = cipher(key,(0,i))
        uint2 a = threefry2x32(0u, 42u, 0u, 0u);
        uint2 b = threefry2x32(0u, 42u, 0u, 1u);
        skey[0] = a.x; skey[1] = a.y; skey[2] = b.x; skey[3] = b.y;
    }
    const float4* xin = (const float4*)(x + row0 * CD);
    #pragma unroll
    for (int i = tid; i < RPB * CD / 4; i += 512)
        ((float4*)&sx[0][0])[i] = xin[i];
    for (int i = tid; i < KCO * HD; i += 512)
        wcs[i >> 6][i & 63] = wc[i];
    __syncthreads();

    int row = (int)row0 + wrp;
    const float* xr = sx[wrp];

    // bg detector (|x| sum over all 128) + per-half squared norms
    float sa = fabsf(xr[lane]) + fabsf(xr[lane+32]) + fabsf(xr[lane+64]) + fabsf(xr[lane+96]);
    float xs = __fadd_rn(__fmul_rn(xr[lane],    xr[lane]),    __fmul_rn(xr[lane+32], xr[lane+32]));
    float xc = __fadd_rn(__fmul_rn(xr[lane+64], xr[lane+64]), __fmul_rn(xr[lane+96], xr[lane+96]));
    #pragma unroll
    for (int o = 16; o > 0; o >>= 1) {
        sa += __shfl_xor_sync(0xffffffffu, sa, o);
        xs = __fadd_rn(xs, __shfl_xor_sync(0xffffffffu, xs, o));
        xc = __fadd_rn(xc, __shfl_xor_sync(0xffffffffu, xc, o));
    }
    bool bg = sa < 1e-6f;
    uint32_t ks0 = skey[0], ks1 = skey[1], kc0 = skey[2], kc1 = skey[3];

    // ---- shape: argmax over 512 codes, 64-code smem tiles ----
    float best = -INFINITY; int bidx = 0;
    for (int tile = 0; tile < 8; ++tile) {
        __syncthreads();
        for (int i = tid; i < 64 * HD; i += 512)
            wt[i >> 6][i & 63] = ws[tile * 64 * HD + i];
        __syncthreads();

        int c0 = tile * 64 + lane, c1 = c0 + 32;
        float a0 = 0.f, a1 = 0.f;
        #pragma unroll
        for (int j = 0; j < HD; j += 4) {
            float4 xv = *(const float4*)&xr[j];
            float4 w0 = *(const float4*)&wt[lane][j];
            float4 w1 = *(const float4*)&wt[lane + 32][j];
            a0 = __fmaf_rn(xv.x, w0.x, a0); a0 = __fmaf_rn(xv.y, w0.y, a0);
            a0 = __fmaf_rn(xv.z, w0.z, a0); a0 = __fmaf_rn(xv.w, w0.w, a0);
            a1 = __fmaf_rn(xv.x, w1.x, a1); a1 = __fmaf_rn(xv.y, w1.y, a1);
            a1 = __fmaf_rn(xv.z, w1.z, a1); a1 = __fmaf_rn(xv.w, w1.w, a1);
        }
        if (bg ? (c0 < 16) : (c0 >= 16)) {
            float g = gumbel_at(ks0, ks1, (unsigned long long)row * KSH + c0);
            float d = __fadd_rn(__fadd_rn(xs, g_ww_s[c0]), -__fmul_rn(2.f, a0));
            float v = __fadd_rn(-d, g);
            if (v > best) { best = v; bidx = c0; }
        }
        if (bg ? (c1 < 16) : (c1 >= 16)) {
            float g = gumbel_at(ks0, ks1, (unsigned long long)row * KSH + c1);
            float d = __fadd_rn(__fadd_rn(xs, g_ww_s[c1]), -__fmul_rn(2.f, a1));
            float v = __fadd_rn(-d, g);
            if (v > best) { best = v; bidx = c1; }
        }
    }
    #pragma unroll
    for (int o = 16; o > 0; o >>= 1) {  // warp argmax, lowest-index tiebreak
        float ov = __shfl_xor_sync(0xffffffffu, best, o);
        int   oi = __shfl_xor_sync(0xffffffffu, bidx, o);
        if (ov > best || (ov == best && oi < bidx)) { best = ov; bidx = oi; }
    }

    // ---- color: 16 codes, one per lane ----
    float cbest = -INFINITY; int cbidx = 0;
    if (lane < KCO) {
        float a = 0.f;
        #pragma unroll
        for (int j = 0; j < HD; j += 4) {
            float4 xv = *(const float4*)&xr[64 + j];
            float4 wv = *(const float4*)&wcs[lane][j];
            a = __fmaf_rn(xv.x, wv.x, a); a = __fmaf_rn(xv.y, wv.y, a);
            a = __fmaf_rn(xv.z, wv.z, a); a = __fmaf_rn(xv.w, wv.w, a);
        }
        float g = gumbel_at(kc0, kc1, (unsigned long long)row * KCO + lane);
        float d = __fadd_rn(__fadd_rn(xc, g_ww_c[lane]), -__fmul_rn(2.f, a));
        cbest = __fadd_rn(-d, g);
        cbidx = lane;
    }
    #pragma unroll
    for (int o = 16; o > 0; o >>= 1) {
        float ov = __shfl_xor_sync(0xffffffffu, cbest, o);
        int   oi = __shfl_xor_sync(0xffffffffu, cbidx, o);
        if (ov > cbest || (ov == cbest && oi < cbidx)) { cbest = ov; cbidx = oi; }
    }

    // ---- outputs ----
    const float* wsel = ws + (size_t)bidx * HD;
    const float* wcel = wc + (size_t)cbidx * HD;
    float* qo = out + (size_t)row * CD;
    float e = 0.f;
    #pragma unroll
    for (int j = lane; j < HD; j += 32) {
        float w0 = wsel[j], w1 = wcel[j];
        qo[j] = w0;
        qo[j + 64] = w1;
        float d0 = w0 - xr[j], d1 = w1 - xr[j + 64];
        e = __fmaf_rn(d0, d0, e);
        e = __fmaf_rn(d1, d1, e);
    }
    #pragma unroll
    for (int o = 16; o > 0; o >>= 1) e += __shfl_xor_sync(0xffffffffu, e, o);

    if (lane == 0) {
        out[IDX_OFF + row] = (float)bidx;
        if (!bg) {
            atomicAdd(&g_usage_s[bidx], 1);
            atomicAdd(&g_usage_c[cbidx], 1);
            atomicAdd(&g_vcount, 1);
            s_loss[wrp] = e;
        } else {
            s_loss[wrp] = 0.f;
        }
    }
    __syncthreads();
    if (tid == 0) {
        double acc = 0.0;
        #pragma unroll
        for (int i = 0; i < RPB; i++) acc += (double)s_loss[i];
        g_loss_part[blockIdx.x] = acc;
    }
}

// ---------------- kernel 2: finalize ----------------
__global__ __launch_bounds__(512) void k_final(float* __restrict__ out) {
    __shared__ double sd[512];
    int t = threadIdx.x;
    double a = 0.0;
    for (int i = t; i < NBLK; i += 512) a += g_loss_part[i];
    sd[t] = a;
    for (int i = t; i < KSH; i += 512) out[US_OFF + i] = (float)g_usage_s[i];
    if (t < KCO) out[UC_OFF + t] = (float)g_usage_c[t];
    __syncthreads();
    if (t == 0) {
        double L = 0.0;
        for (int i = 0; i < 512; i++) L += sd[i];
        double vc = (double)g_vcount;
        out[LOSS_OFF] = (float)(1.25 * L / (vc * 128.0));
        double e = 0.0;
        for (int i = 0; i < KSH; i++) {
            double p = (double)g_usage_s[i] / vc;
            e += p * log(p + 1e-10);
        }
        out[PS_OFF] = (float)exp(-e);
        e = 0.0;
        for (int i = 0; i < KCO; i++) {
            double p = (double)g_usage_c[i] / vc;
            e += p * log(p + 1e-10);
        }
        out[PC_OFF] = (float)exp(-e);
    }
}

extern "C" void kernel_launch(void* const* d_in, const int* in_sizes, int n_in,
                              void* d_out, int out_size) {
    const float* x  = (const float*)d_in[0];   // inputs [16,4096,128]
    const float* ws = (const float*)d_in[2];   // w_shape [512,64]
    const float* wc = (const float*)d_in[3];   // w_color [16,64]
    float* out = (float*)d_out;
    k_init<<<1, 512>>>(ws, wc);
    k_main<<<NBLK, 512>>>(x, ws, wc, out);
    k_final<<<1, 512>>>(out);
}

// round 3
// speedup vs baseline: 4.2037x; 4.2037x over previous
#include <cuda_runtime.h>
#include <stdint.h>
#include <math.h>

#define T_ROWS 65536
#define CD 128
#define HD 64
#define KSH 512
#define KCO 16
#define RPB 64                 // rows per block
#define NBLK (T_ROWS / RPB)    // 1024

#define LOSS_OFF 8388608ul
#define PS_OFF   8388609ul
#define PC_OFF   8388610ul
#define IDX_OFF  8388611ul
#define US_OFF   8454147ul
#define UC_OFF   8454659ul

// padded strides (floats): 68 floats = 17 float4 (odd) -> conflict-free rows
#define XP 68

__device__ float  g_ww_s[KSH];
__device__ float  g_ww_c[KCO];
__device__ int    g_usage_s[KSH];
__device__ int    g_usage_c[KCO];
__device__ int    g_vcount;
__device__ double g_loss_part[NBLK];

// ---------------- threefry2x32 (JAX partitionable) ----------------
__device__ __forceinline__ uint32_t rotl32(uint32_t x, int d) {
    return (x << d) | (x >> (32 - d));
}
__device__ __forceinline__ void tf_r(uint32_t& x0, uint32_t& x1, int r) {
    x0 += x1; x1 = rotl32(x1, r); x1 ^= x0;
}
__device__ __forceinline__ uint2 threefry2x32(uint32_t k0, uint32_t k1,
                                              uint32_t x0, uint32_t x1) {
    uint32_t k2 = k0 ^ k1 ^ 0x1BD11BDAu;
    x0 += k0; x1 += k1;
    tf_r(x0,x1,13); tf_r(x0,x1,15); tf_r(x0,x1,26); tf_r(x0,x1,6);
    x0 += k1; x1 += k2 + 1u;
    tf_r(x0,x1,17); tf_r(x0,x1,29); tf_r(x0,x1,16); tf_r(x0,x1,24);
    x0 += k2; x1 += k0 + 2u;
    tf_r(x0,x1,13); tf_r(x0,x1,15); tf_r(x0,x1,26); tf_r(x0,x1,6);
    x0 += k0; x1 += k1 + 3u;
    tf_r(x0,x1,17); tf_r(x0,x1,29); tf_r(x0,x1,16); tf_r(x0,x1,24);
    x0 += k1; x1 += k2 + 4u;
    tf_r(x0,x1,13); tf_r(x0,x1,15); tf_r(x0,x1,26); tf_r(x0,x1,6);
    x0 += k2; x1 += k0 + 5u;
    return make_uint2(x0, x1);
}

// bit-identical to the R1 passing version (hi counter word is 0: idx < 2^25)
__device__ __forceinline__ float gumbel_at(uint32_t k0, uint32_t k1, uint32_t idx) {
    uint2 r = threefry2x32(k0, k1, 0u, idx);
    uint32_t bits = r.x ^ r.y;
    const float TINY = 1.17549435e-38f;
    float f = __uint_as_float(0x3F800000u | (bits >> 9)) - 1.0f;
    float u = fmaxf(TINY, __fadd_rn(f, TINY));
    return -logf(-logf(u));
}

// ---------------- kernel 0: code norms + zero accumulators ----------------
// one warp per code row, coalesced float2 loads
__global__ __launch_bounds__(256) void k_init(const float* __restrict__ ws,
                                              const float* __restrict__ wc) {
    int gw = (blockIdx.x * 256 + threadIdx.x) >> 5;
    int lane = threadIdx.x & 31;
    if (gw < KSH + KCO) {
        const float* src = (gw < KSH) ? (ws + gw * HD) : (wc + (gw - KSH) * HD);
        float2 v = ((const float2*)src)[lane];
        float s = __fadd_rn(__fmul_rn(v.x, v.x), __fmul_rn(v.y, v.y));
        #pragma unroll
        for (int o = 16; o > 0; o >>= 1)
            s = __fadd_rn(s, __shfl_xor_sync(0xffffffffu, s, o));
        if (lane == 0) {
            if (gw < KSH) g_ww_s[gw] = s;
            else          g_ww_c[gw - KSH] = s;
        }
    }
    if (blockIdx.x == 0) {
        int t = threadIdx.x;
        for (int i = t; i < KSH; i += 256) g_usage_s[i] = 0;
        if (t < KCO) g_usage_c[t] = 0;
        if (t == 0) g_vcount = 0;
    }
}

// ---------------- kernel 1: main ----------------
// 64 rows/block, 256 threads. ci = tid&15 (code group), ri = tid>>4 (row group).
// Thread tile: rows {16q+ri}, shape codes {tile*128 + ci + 16m}.
__global__ __launch_bounds__(256, 2) void k_main(const float* __restrict__ x,
                                                 const float* __restrict__ ws,
                                                 const float* __restrict__ wc,
                                                 float* __restrict__ out) {
    extern __shared__ __align__(16) char smem_raw[];
    float* sXs = (float*)smem_raw;            // 64*68
    float* sXc = sXs + 64 * XP;               // 64*68
    float* sW  = sXc + 64 * XP;               // 128*68
    float* sWc = sW  + 128 * XP;              // 16*68
    float* sWW = sWc + 16 * XP;               // 128
    float* sWWc = sWW + 128;                  // 16
    float* sXN = sWWc + 16;                   // 64
    float* sCN = sXN + 64;                    // 64
    int*   sBG = (int*)(sCN + 64);            // 64
    int*   sSI = sBG + 64;                    // 64
    int*   sCI = sSI + 64;                    // 64
    uint32_t* sKey = (uint32_t*)(sCI + 64);   // 4
    float* sLossW = (float*)(sKey + 4);       // 8
    int*   sVC = (int*)(sLossW + 8);          // 1
    int*   sFG = sVC + 1;                     // 1

    int tid = threadIdx.x, lane = tid & 31, w = tid >> 5;
    int ci = tid & 15, ri = tid >> 4;
    int rowbase = blockIdx.x * RPB;

    if (tid == 0) {
        uint2 a = threefry2x32(0u, 42u, 0u, 0u);   // ks
        uint2 b = threefry2x32(0u, 42u, 0u, 1u);   // kc
        sKey[0] = a.x; sKey[1] = a.y; sKey[2] = b.x; sKey[3] = b.y;
        *sVC = 0; *sFG = 0;
    }

    // load X tile: 64 rows x 128 -> split halves into padded smem
    const float4* gx = (const float4*)(x + (size_t)rowbase * CD);
    #pragma unroll
    for (int i = tid; i < RPB * 32; i += 256) {
        float4 v = gx[i];
        int r = i >> 5, c4 = i & 31;
        if (c4 < 16) ((float4*)(sXs + r * XP))[c4] = v;
        else         ((float4*)(sXc + r * XP))[c4 - 16] = v;
    }
    // color codebook + norms
    {
        int i = tid;
        if (i < 256) {
            float4 v = ((const float4*)wc)[i];
            ((float4*)(sWc + (i >> 4) * XP))[i & 15] = v;
        }
        if (tid < KCO) sWWc[tid] = g_ww_c[tid];
    }
    __syncthreads();

    // per-row bg + half-norms: warp w -> rows w*8..+7, 4 lanes per row
    {
        int r = w * 8 + (lane >> 2);
        int part = lane & 3;
        float sa = 0.f, ss = 0.f, sc = 0.f;
        #pragma unroll
        for (int j = 0; j < 16; j++) {
            float a = sXs[r * XP + part * 16 + j];
            float b = sXc[r * XP + part * 16 + j];
            sa += fabsf(a) + fabsf(b);
            ss = __fmaf_rn(a, a, ss);
            sc = __fmaf_rn(b, b, sc);
        }
        #pragma unroll
        for (int o = 1; o < 4; o <<= 1) {
            sa += __shfl_xor_sync(0xffffffffu, sa, o);
            ss += __shfl_xor_sync(0xffffffffu, ss, o);
            sc += __shfl_xor_sync(0xffffffffu, sc, o);
        }
        if (part == 0) {
            int b = (sa < 1e-6f);
            sBG[r] = b; sXN[r] = ss; sCN[r] = sc;
            if (!b) *sFG = 1;
        }
    }
    __syncthreads();
    int anyfg = *sFG;
    uint32_t ks0 = sKey[0], ks1 = sKey[1], kc0 = sKey[2], kc1 = sKey[3];

    float best[4];  int bidx[4];
    #pragma unroll
    for (int q = 0; q < 4; q++) { best[q] = -INFINITY; bidx[q] = 0; }

    int ntile = anyfg ? 4 : 1;
    for (int tile = 0; tile < ntile; ++tile) {
        if (anyfg) {
            const float4* gw = (const float4*)(ws + (size_t)tile * 128 * HD);
            #pragma unroll
            for (int i = tid; i < 128 * 16; i += 256) {
                float4 v = gw[i];
                ((float4*)(sW + (i >> 4) * XP))[i & 15] = v;
            }
        }
        if (tid < 128) sWW[tid] = g_ww_s[tile * 128 + tid];
        __syncthreads();

        float acc[4][8];
        #pragma unroll
        for (int q = 0; q < 4; q++)
            #pragma unroll
            for (int m = 0; m < 8; m++) acc[q][m] = 0.f;

        if (anyfg) {
            #pragma unroll
            for (int k4 = 0; k4 < 16; k4++) {
                float4 xv[4];
                #pragma unroll
                for (int q = 0; q < 4; q++)
                    xv[q] = ((const float4*)(sXs + (16 * q + ri) * XP))[k4];
                #pragma unroll
                for (int m = 0; m < 8; m++) {
                    float4 wv = ((const float4*)(sW + (ci + 16 * m) * XP))[k4];
                    #pragma unroll
                    for (int q = 0; q < 4; q++) {
                        acc[q][m] = __fmaf_rn(xv[q].x, wv.x, acc[q][m]);
                        acc[q][m] = __fmaf_rn(xv[q].y, wv.y, acc[q][m]);
                        acc[q][m] = __fmaf_rn(xv[q].z, wv.z, acc[q][m]);
                        acc[q][m] = __fmaf_rn(xv[q].w, wv.w, acc[q][m]);
                    }
                }
            }
        }

        // evaluate logits + gumbel, fold into per-row argmax
        #pragma unroll
        for (int q = 0; q < 4; q++) {
            int r = 16 * q + ri;
            int bg = sBG[r];
            float xs = sXN[r];
            uint32_t rowoff = (uint32_t)(rowbase + r) << 9;  // *512
            #pragma unroll
            for (int m = 0; m < 8; m++) {
                int code = tile * 128 + ci + 16 * m;
                bool allowed = bg ? (code < KCO) : (code >= KCO);
                if (allowed) {
                    float g = gumbel_at(ks0, ks1, rowoff + (uint32_t)code);
                    float d = __fadd_rn(__fadd_rn(xs, sWW[ci + 16 * m]),
                                        -__fmul_rn(2.f, acc[q][m]));
                    float v = __fadd_rn(-d, g);
                    if (v > best[q]) { best[q] = v; bidx[q] = code; }
                }
            }
        }
        __syncthreads();  // before sW/sWW overwrite next tile
    }

    // ---- color: thread handles code ci for its 4 rows ----
    float cbest[4]; int cbidx[4];
    #pragma unroll
    for (int q = 0; q < 4; q++) {
        int r = 16 * q + ri;
        float a = 0.f;
        #pragma unroll
        for (int k4 = 0; k4 < 16; k4++) {
            float4 xv = ((const float4*)(sXc + r * XP))[k4];
            float4 wv = ((const float4*)(sWc + ci * XP))[k4];
            a = __fmaf_rn(xv.x, wv.x, a);
            a = __fmaf_rn(xv.y, wv.y, a);
            a = __fmaf_rn(xv.z, wv.z, a);
            a = __fmaf_rn(xv.w, wv.w, a);
        }
        float g = gumbel_at(kc0, kc1, ((uint32_t)(rowbase + r) << 4) + (uint32_t)ci);
        float d = __fadd_rn(__fadd_rn(sCN[r], sWWc[ci]), -__fmul_rn(2.f, a));
        cbest[q] = __fadd_rn(-d, g);
        cbidx[q] = ci;
    }

    // ---- argmax reduce across the 16 ci lanes (contiguous in half-warp) ----
    #pragma unroll
    for (int o = 8; o > 0; o >>= 1) {
        #pragma unroll
        for (int q = 0; q < 4; q++) {
            float ov = __shfl_xor_sync(0xffffffffu, best[q], o);
            int   oi = __shfl_xor_sync(0xffffffffu, bidx[q], o);
            if (ov > best[q] || (ov == best[q] && oi < bidx[q])) { best[q] = ov; bidx[q] = oi; }
            float cv = __shfl_xor_sync(0xffffffffu, cbest[q], o);
            int   cb = __shfl_xor_sync(0xffffffffu, cbidx[q], o);
            if (cv > cbest[q] || (cv == cbest[q] && cb < cbidx[q])) { cbest[q] = cv; cbidx[q] = cb; }
        }
    }
    if ((lane & 15) == 0) {
        #pragma unroll
        for (int q = 0; q < 4; q++) {
            int r = 16 * q + ri;
            sSI[r] = bidx[q];
            sCI[r] = cbidx[q];
        }
    }
    __syncthreads();

    // ---- outputs: quantized rows, idx, usage, loss ----
    float eacc = 0.f; int vcnt = 0;
    for (int t = 0; t < 8; t++) {
        int r = w * 8 + t;
        int widx = sSI[r], cidx = sCI[r];
        size_t grow = (size_t)rowbase + r;
        float4 wv, xv;
        if (lane < 16) {
            wv = ((const float4*)(ws + widx * HD))[lane];
            xv = ((const float4*)(sXs + r * XP))[lane];
        } else {
            wv = ((const float4*)(wc + cidx * HD))[lane - 16];
            xv = ((const float4*)(sXc + r * XP))[lane - 16];
        }
        ((float4*)out)[grow * 32 + lane] = wv;
        float dx = wv.x - xv.x, dy = wv.y - xv.y, dz = wv.z - xv.z, dw = wv.w - xv.w;
        float e = dx * dx + dy * dy + dz * dz + dw * dw;
        #pragma unroll
        for (int o = 16; o > 0; o >>= 1)
            e += __shfl_xor_sync(0xffffffffu, e, o);
        if (lane == 0) {
            out[IDX_OFF + grow] = (float)widx;
            if (!sBG[r]) {
                atomicAdd(&g_usage_s[widx], 1);
                atomicAdd(&g_usage_c[cidx], 1);
                vcnt++;
                eacc += e;
            }
        }
    }
    if (lane == 0) {
        sLossW[w] = eacc;
        atomicAdd(sVC, vcnt);
    }
    __syncthreads();
    if (tid == 0) {
        double L = 0.0;
        #pragma unroll
        for (int i = 0; i < 8; i++) L += (double)sLossW[i];
        g_loss_part[blockIdx.x] = L;
        atomicAdd(&g_vcount, *sVC);
    }
}

// ---------------- kernel 2: finalize ----------------
__global__ __launch_bounds__(512) void k_final(float* __restrict__ out) {
    __shared__ double sd[512];
    int t = threadIdx.x;
    double a = 0.0;
    for (int i = t; i < NBLK; i += 512) a += g_loss_part[i];
    sd[t] = a; __syncthreads();
    for (int s = 256; s > 0; s >>= 1) { if (t < s) sd[t] += sd[t + s]; __syncthreads(); }
    double vc = (double)g_vcount;
    if (t == 0) out[LOSS_OFF] = (float)(1.25 * sd[0] / (vc * 128.0));
    __syncthreads();

    double e = 0.0;
    {
        double p = (double)g_usage_s[t] / vc;
        e = p * log(p + 1e-10);
        out[US_OFF + t] = (float)g_usage_s[t];
    }
    sd[t] = e; __syncthreads();
    for (int s = 256; s > 0; s >>= 1) { if (t < s) sd[t] += sd[t + s]; __syncthreads(); }
    if (t == 0) out[PS_OFF] = (float)exp(-sd[0]);
    __syncthreads();

    double ec = 0.0;
    if (t < KCO) {
        double p = (double)g_usage_c[t] / vc;
        ec = p * log(p + 1e-10);
        out[UC_OFF + t] = (float)g_usage_c[t];
    }
    sd[t] = ec; __syncthreads();
    for (int s = 256; s > 0; s >>= 1) { if (t < s) sd[t] += sd[t + s]; __syncthreads(); }
    if (t == 0) out[PC_OFF] = (float)exp(-sd[0]);
}

#define SMEM_BYTES ((64*XP + 64*XP + 128*XP + 16*XP + 128 + 16 + 64 + 64) * 4 \
                    + (64 + 64 + 64 + 4 + 8 + 1 + 1) * 4 + 64)

extern "C" void kernel_launch(void* const* d_in, const int* in_sizes, int n_in,
                              void* d_out, int out_size) {
    const float* x  = (const float*)d_in[0];   // inputs [16,4096,128]
    const float* ws = (const float*)d_in[2];   // w_shape [512,64]
    const float* wc = (const float*)d_in[3];   // w_color [16,64]
    float* out = (float*)d_out;
    cudaFuncSetAttribute(k_main, cudaFuncAttributeMaxDynamicSharedMemorySize, SMEM_BYTES);
    k_init<<<66, 256>>>(ws, wc);
    k_main<<<NBLK, 256, SMEM_BYTES>>>(x, ws, wc, out);
    k_final<<<1, 512>>>(out);
}

// round 4
// speedup vs baseline: 4.5548x; 1.0835x over previous
#include <cuda_runtime.h>
#include <stdint.h>
#include <math.h>

#define T_ROWS 65536
#define CD 128
#define HD 64
#define KSH 512
#define KCO 16
#define RPB 64                 // rows per block
#define NBLK (T_ROWS / RPB)    // 1024

#define LOSS_OFF 8388608ul
#define PS_OFF   8388609ul
#define PC_OFF   8388610ul
#define IDX_OFF  8388611ul
#define US_OFF   8454147ul
#define UC_OFF   8454659ul

// padded stride (floats): 68 = 17 float4 (odd) -> conflict-free code rows
#define XP 68

__device__ float  g_ww_s[KSH];
__device__ float  g_ww_c[KCO];
__device__ int    g_usage_s[KSH];
__device__ int    g_usage_c[KCO];
__device__ int    g_vcount;
__device__ double g_loss_part[NBLK];

// ---------------- packed f32x2 FMA (FFMA2 — PTX-only) ----------------
__device__ __forceinline__ unsigned long long ffma2(unsigned long long a,
                                                    unsigned long long b,
                                                    unsigned long long c) {
    unsigned long long d;
    asm("fma.rn.f32x2 %0, %1, %2, %3;" : "=l"(d) : "l"(a), "l"(b), "l"(c));
    return d;
}
__device__ __forceinline__ float fold2(unsigned long long a) {
    float2 p = *(float2*)&a;
    return __fadd_rn(p.x, p.y);
}

// ---------------- threefry2x32 (JAX partitionable) ----------------
__device__ __forceinline__ uint32_t rotl32(uint32_t x, int d) {
    return (x << d) | (x >> (32 - d));
}
__device__ __forceinline__ void tf_r(uint32_t& x0, uint32_t& x1, int r) {
    x0 += x1; x1 = rotl32(x1, r); x1 ^= x0;
}
__device__ __forceinline__ uint2 threefry2x32(uint32_t k0, uint32_t k1,
                                              uint32_t x0, uint32_t x1) {
    uint32_t k2 = k0 ^ k1 ^ 0x1BD11BDAu;
    x0 += k0; x1 += k1;
    tf_r(x0,x1,13); tf_r(x0,x1,15); tf_r(x0,x1,26); tf_r(x0,x1,6);
    x0 += k1; x1 += k2 + 1u;
    tf_r(x0,x1,17); tf_r(x0,x1,29); tf_r(x0,x1,16); tf_r(x0,x1,24);
    x0 += k2; x1 += k0 + 2u;
    tf_r(x0,x1,13); tf_r(x0,x1,15); tf_r(x0,x1,26); tf_r(x0,x1,6);
    x0 += k0; x1 += k1 + 3u;
    tf_r(x0,x1,17); tf_r(x0,x1,29); tf_r(x0,x1,16); tf_r(x0,x1,24);
    x0 += k1; x1 += k2 + 4u;
    tf_r(x0,x1,13); tf_r(x0,x1,15); tf_r(x0,x1,26); tf_r(x0,x1,6);
    x0 += k2; x1 += k0 + 5u;
    return make_uint2(x0, x1);
}

__device__ __forceinline__ float gumbel_at(uint32_t k0, uint32_t k1, uint32_t idx) {
    uint2 r = threefry2x32(k0, k1, 0u, idx);
    uint32_t bits = r.x ^ r.y;
    const float TINY = 1.17549435e-38f;
    float f = __uint_as_float(0x3F800000u | (bits >> 9)) - 1.0f;
    float u = fmaxf(TINY, __fadd_rn(f, TINY));
    return -logf(-logf(u));
}

// ---------------- kernel 0: code norms + zero accumulators ----------------
__global__ __launch_bounds__(256) void k_init(const float* __restrict__ ws,
                                              const float* __restrict__ wc) {
    int gw = (blockIdx.x * 256 + threadIdx.x) >> 5;
    int lane = threadIdx.x & 31;
    if (gw < KSH + KCO) {
        const float* src = (gw < KSH) ? (ws + gw * HD) : (wc + (gw - KSH) * HD);
        float2 v = ((const float2*)src)[lane];
        float s = __fadd_rn(__fmul_rn(v.x, v.x), __fmul_rn(v.y, v.y));
        #pragma unroll
        for (int o = 16; o > 0; o >>= 1)
            s = __fadd_rn(s, __shfl_xor_sync(0xffffffffu, s, o));
        if (lane == 0) {
            if (gw < KSH) g_ww_s[gw] = s;
            else          g_ww_c[gw - KSH] = s;
        }
    }
    if (blockIdx.x == 0) {
        int t = threadIdx.x;
        for (int i = t; i < KSH; i += 256) g_usage_s[i] = 0;
        if (t < KCO) g_usage_c[t] = 0;
        if (t == 0) g_vcount = 0;
    }
}

// ---------------- kernel 1: main ----------------
__global__ __launch_bounds__(256, 2) void k_main(const float* __restrict__ x,
                                                 const float* __restrict__ ws,
                                                 const float* __restrict__ wc,
                                                 float* __restrict__ out) {
    extern __shared__ __align__(16) char smem_raw[];
    float* sXs = (float*)smem_raw;            // 64*68
    float* sXc = sXs + 64 * XP;               // 64*68
    float* sW  = sXc + 64 * XP;               // 128*68
    float* sWc = sW  + 128 * XP;              // 16*68
    float* sWW = sWc + 16 * XP;               // 128
    float* sWWc = sWW + 128;                  // 16
    float* sXN = sWWc + 16;                   // 64
    float* sCN = sXN + 64;                    // 64
    int*   sBG = (int*)(sCN + 64);            // 64
    int*   sSI = sBG + 64;                    // 64
    int*   sCI = sSI + 64;                    // 64
    uint32_t* sKey = (uint32_t*)(sCI + 64);   // 4
    float* sLossW = (float*)(sKey + 4);       // 8
    int*   sVC = (int*)(sLossW + 8);          // 1
    int*   sFG = sVC + 1;                     // 1

    int tid = threadIdx.x, lane = tid & 31, w = tid >> 5;
    int ci = tid & 15, ri = tid >> 4;
    int rowbase = blockIdx.x * RPB;

    if (tid == 0) {
        uint2 a = threefry2x32(0u, 42u, 0u, 0u);   // ks
        uint2 b = threefry2x32(0u, 42u, 0u, 1u);   // kc
        sKey[0] = a.x; sKey[1] = a.y; sKey[2] = b.x; sKey[3] = b.y;
        *sVC = 0; *sFG = 0;
    }

    // load X tile: 64 rows x 128 -> split halves into padded smem
    const float4* gx = (const float4*)(x + (size_t)rowbase * CD);
    #pragma unroll
    for (int i = tid; i < RPB * 32; i += 256) {
        float4 v = gx[i];
        int r = i >> 5, c4 = i & 31;
        if (c4 < 16) ((float4*)(sXs + r * XP))[c4] = v;
        else         ((float4*)(sXc + r * XP))[c4 - 16] = v;
    }
    // color codebook + norms
    {
        float4 v = ((const float4*)wc)[tid & 255];
        ((float4*)(sWc + ((tid & 255) >> 4) * XP))[tid & 15] = v;
        if (tid < KCO) sWWc[tid] = g_ww_c[tid];
    }
    __syncthreads();

    // per-row bg + half-norms: warp w -> rows w*8..+7, 4 lanes per row
    {
        int r = w * 8 + (lane >> 2);
        int part = lane & 3;
        float sa = 0.f, ss = 0.f, sc = 0.f;
        #pragma unroll
        for (int j = 0; j < 16; j++) {
            float a = sXs[r * XP + part * 16 + j];
            float b = sXc[r * XP + part * 16 + j];
            sa += fabsf(a) + fabsf(b);
            ss = __fmaf_rn(a, a, ss);
            sc = __fmaf_rn(b, b, sc);
        }
        #pragma unroll
        for (int o = 1; o < 4; o <<= 1) {
            sa += __shfl_xor_sync(0xffffffffu, sa, o);
            ss += __shfl_xor_sync(0xffffffffu, ss, o);
            sc += __shfl_xor_sync(0xffffffffu, sc, o);
        }
        if (part == 0) {
            int b = (sa < 1e-6f);
            sBG[r] = b; sXN[r] = ss; sCN[r] = sc;
            if (!b) *sFG = 1;
        }
    }
    __syncthreads();
    int anyfg = *sFG;
    uint32_t ks0 = sKey[0], ks1 = sKey[1], kc0 = sKey[2], kc1 = sKey[3];

    float best[4];  int bidx[4];
    #pragma unroll
    for (int q = 0; q < 4; q++) { best[q] = -INFINITY; bidx[q] = 0; }

    int ntile = anyfg ? 4 : 1;
    for (int tile = 0; tile < ntile; ++tile) {
        if (anyfg) {
            const float4* gw = (const float4*)(ws + (size_t)tile * 128 * HD);
            #pragma unroll
            for (int i = tid; i < 128 * 16; i += 256) {
                float4 v = gw[i];
                ((float4*)(sW + (i >> 4) * XP))[i & 15] = v;
            }
        }
        if (tid < 128) sWW[tid] = g_ww_s[tile * 128 + tid];
        __syncthreads();

        // packed f32x2 accumulators: lo = even-k partial, hi = odd-k partial
        unsigned long long acc[4][8];
        #pragma unroll
        for (int q = 0; q < 4; q++)
            #pragma unroll
            for (int m = 0; m < 8; m++) acc[q][m] = 0ull;

        if (anyfg) {
            #pragma unroll
            for (int k4 = 0; k4 < 16; k4++) {
                ulonglong2 xv[4];
                #pragma unroll
                for (int q = 0; q < 4; q++)
                    xv[q] = ((const ulonglong2*)(sXs + (16 * q + ri) * XP))[k4];
                #pragma unroll
                for (int m = 0; m < 8; m++) {
                    ulonglong2 wv = ((const ulonglong2*)(sW + (ci + 16 * m) * XP))[k4];
                    #pragma unroll
                    for (int q = 0; q < 4; q++) {
                        acc[q][m] = ffma2(xv[q].x, wv.x, acc[q][m]);
                        acc[q][m] = ffma2(xv[q].y, wv.y, acc[q][m]);
                    }
                }
            }
        }

        // evaluate logits + gumbel, fold into per-row argmax
        #pragma unroll
        for (int q = 0; q < 4; q++) {
            int r = 16 * q + ri;
            int bg = sBG[r];
            float xs = sXN[r];
            uint32_t rowoff = (uint32_t)(rowbase + r) << 9;  // *512
            #pragma unroll
            for (int m = 0; m < 8; m++) {
                int code = tile * 128 + ci + 16 * m;
                bool allowed = bg ? (code < KCO) : (code >= KCO);
                if (allowed) {
                    float a = fold2(acc[q][m]);
                    float g = gumbel_at(ks0, ks1, rowoff + (uint32_t)code);
                    float d = __fadd_rn(__fadd_rn(xs, sWW[ci + 16 * m]),
                                        -__fmul_rn(2.f, a));
                    float v = __fadd_rn(-d, g);
                    if (v > best[q]) { best[q] = v; bidx[q] = code; }
                }
            }
        }
        __syncthreads();  // before sW/sWW overwrite next tile
    }

    // ---- color: thread handles code ci for its 4 rows (packed fma) ----
    float cbest[4]; int cbidx[4];
    #pragma unroll
    for (int q = 0; q < 4; q++) {
        int r = 16 * q + ri;
        unsigned long long a2 = 0ull;
        #pragma unroll
        for (int k4 = 0; k4 < 16; k4++) {
            ulonglong2 xv = ((const ulonglong2*)(sXc + r * XP))[k4];
            ulonglong2 wv = ((const ulonglong2*)(sWc + ci * XP))[k4];
            a2 = ffma2(xv.x, wv.x, a2);
            a2 = ffma2(xv.y, wv.y, a2);
        }
        float a = fold2(a2);
        float g = gumbel_at(kc0, kc1, ((uint32_t)(rowbase + r) << 4) + (uint32_t)ci);
        float d = __fadd_rn(__fadd_rn(sCN[r], sWWc[ci]), -__fmul_rn(2.f, a));
        cbest[q] = __fadd_rn(-d, g);
        cbidx[q] = ci;
    }

    // ---- argmax reduce across the 16 ci lanes ----
    #pragma unroll
    for (int o = 8; o > 0; o >>= 1) {
        #pragma unroll
        for (int q = 0; q < 4; q++) {
            float ov = __shfl_xor_sync(0xffffffffu, best[q], o);
            int   oi = __shfl_xor_sync(0xffffffffu, bidx[q], o);
            if (ov > best[q] || (ov == best[q] && oi < bidx[q])) { best[q] = ov; bidx[q] = oi; }
            float cv = __shfl_xor_sync(0xffffffffu, cbest[q], o);
            int   cb = __shfl_xor_sync(0xffffffffu, cbidx[q], o);
            if (cv > cbest[q] || (cv == cbest[q] && cb < cbidx[q])) { cbest[q] = cv; cbidx[q] = cb; }
        }
    }
    if ((lane & 15) == 0) {
        #pragma unroll
        for (int q = 0; q < 4; q++) {
            int r = 16 * q + ri;
            sSI[r] = bidx[q];
            sCI[r] = cbidx[q];
        }
    }
    __syncthreads();

    // ---- outputs: quantized rows, idx, usage, loss ----
    float eacc = 0.f; int vcnt = 0;
    for (int t = 0; t < 8; t++) {
        int r = w * 8 + t;
        int widx = sSI[r], cidx = sCI[r];
        size_t grow = (size_t)rowbase + r;
        float4 wv, xv;
        if (lane < 16) {
            wv = ((const float4*)(ws + widx * HD))[lane];
            xv = ((const float4*)(sXs + r * XP))[lane];
        } else {
            wv = ((const float4*)(wc + cidx * HD))[lane - 16];
            xv = ((const float4*)(sXc + r * XP))[lane - 16];
        }
        ((float4*)out)[grow * 32 + lane] = wv;
        float dx = wv.x - xv.x, dy = wv.y - xv.y, dz = wv.z - xv.z, dw = wv.w - xv.w;
        float e = dx * dx + dy * dy + dz * dz + dw * dw;
        #pragma unroll
        for (int o = 16; o > 0; o >>= 1)
            e += __shfl_xor_sync(0xffffffffu, e, o);
        if (lane == 0) {
            out[IDX_OFF + grow] = (float)widx;
            if (!sBG[r]) {
                atomicAdd(&g_usage_s[widx], 1);
                atomicAdd(&g_usage_c[cidx], 1);
                vcnt++;
                eacc += e;
            }
        }
    }
    if (lane == 0) {
        sLossW[w] = eacc;
        atomicAdd(sVC, vcnt);
    }
    __syncthreads();
    if (tid == 0) {
        double L = 0.0;
        #pragma unroll
        for (int i = 0; i < 8; i++) L += (double)sLossW[i];
        g_loss_part[blockIdx.x] = L;
        atomicAdd(&g_vcount, *sVC);
    }
}

// ---------------- kernel 2: finalize ----------------
__global__ __launch_bounds__(512) void k_final(float* __restrict__ out) {
    __shared__ double sd[512];
    int t = threadIdx.x;
    double a = 0.0;
    for (int i = t; i < NBLK; i += 512) a += g_loss_part[i];
    sd[t] = a; __syncthreads();
    for (int s = 256; s > 0; s >>= 1) { if (t < s) sd[t] += sd[t + s]; __syncthreads(); }
    double vc = (double)g_vcount;
    if (t == 0) out[LOSS_OFF] = (float)(1.25 * sd[0] / (vc * 128.0));
    __syncthreads();

    double e = 0.0;
    {
        double p = (double)g_usage_s[t] / vc;
        e = p * log(p + 1e-10);
        out[US_OFF + t] = (float)g_usage_s[t];
    }
    sd[t] = e; __syncthreads();
    for (int s = 256; s > 0; s >>= 1) { if (t < s) sd[t] += sd[t + s]; __syncthreads(); }
    if (t == 0) out[PS_OFF] = (float)exp(-sd[0]);
    __syncthreads();

    double ec = 0.0;
    if (t < KCO) {
        double p = (double)g_usage_c[t] / vc;
        ec = p * log(p + 1e-10);
        out[UC_OFF + t] = (float)g_usage_c[t];
    }
    sd[t] = ec; __syncthreads();
    for (int s = 256; s > 0; s >>= 1) { if (t < s) sd[t] += sd[t + s]; __syncthreads(); }
    if (t == 0) out[PC_OFF] = (float)exp(-sd[0]);
}

#define SMEM_BYTES ((64*XP + 64*XP + 128*XP + 16*XP + 128 + 16 + 64 + 64) * 4 \
                    + (64 + 64 + 64 + 4 + 8 + 1 + 1) * 4 + 64)

extern "C" void kernel_launch(void* const* d_in, const int* in_sizes, int n_in,
                              void* d_out, int out_size) {
    const float* x  = (const float*)d_in[0];   // inputs [16,4096,128]
    const float* ws = (const float*)d_in[2];   // w_shape [512,64]
    const float* wc = (const float*)d_in[3];   // w_color [16,64]
    float* out = (float*)d_out;
    cudaFuncSetAttribute(k_main, cudaFuncAttributeMaxDynamicSharedMemorySize, SMEM_BYTES);
    k_init<<<66, 256>>>(ws, wc);
    k_main<<<NBLK, 256, SMEM_BYTES>>>(x, ws, wc, out);
    k_final<<<1, 512>>>(out);
}

// round 5
// speedup vs baseline: 4.5981x; 1.0095x over previous
#include <cuda_runtime.h>
#include <stdint.h>
#include <math.h>

#define T_ROWS 65536
#define CD 128
#define HD 64
#define KSH 512
#define KCO 16
#define RPB 64                 // rows per block
#define NBLK (T_ROWS / RPB)    // 1024

#define LOSS_OFF 8388608ul
#define PS_OFF   8388609ul
#define PC_OFF   8388610ul
#define IDX_OFF  8388611ul
#define US_OFF   8454147ul
#define UC_OFF   8454659ul

// padded stride (floats): 68 = 17 float4 (odd) -> conflict-free code rows
#define XP 68

// screening gap: 2*eps with eps ~ 4.5e-5 MUFU-path bound, padded
#define GAP 2.5e-4f

__device__ int    g_usage_s[KSH];     // zero-initialized at load; self-resetting
__device__ int    g_usage_c[KCO];
__device__ int    g_vcount;
__device__ int    g_ticket;
__device__ double g_loss_part[NBLK];

// ---------------- packed f32x2 FMA (FFMA2 — PTX-only) ----------------
__device__ __forceinline__ unsigned long long ffma2(unsigned long long a,
                                                    unsigned long long b,
                                                    unsigned long long c) {
    unsigned long long d;
    asm("fma.rn.f32x2 %0, %1, %2, %3;" : "=l"(d) : "l"(a), "l"(b), "l"(c));
    return d;
}
__device__ __forceinline__ float fold2(unsigned long long a) {
    float2 p = *(float2*)&a;
    return __fadd_rn(p.x, p.y);
}

// ---------------- threefry2x32 (JAX partitionable) ----------------
__device__ __forceinline__ uint32_t rotl32(uint32_t x, int d) {
    return (x << d) | (x >> (32 - d));
}
__device__ __forceinline__ void tf_r(uint32_t& x0, uint32_t& x1, int r) {
    x0 += x1; x1 = rotl32(x1, r); x1 ^= x0;
}
__device__ __forceinline__ uint2 threefry2x32(uint32_t k0, uint32_t k1,
                                              uint32_t x0, uint32_t x1) {
    uint32_t k2 = k0 ^ k1 ^ 0x1BD11BDAu;
    x0 += k0; x1 += k1;
    tf_r(x0,x1,13); tf_r(x0,x1,15); tf_r(x0,x1,26); tf_r(x0,x1,6);
    x0 += k1; x1 += k2 + 1u;
    tf_r(x0,x1,17); tf_r(x0,x1,29); tf_r(x0,x1,16); tf_r(x0,x1,24);
    x0 += k2; x1 += k0 + 2u;
    tf_r(x0,x1,13); tf_r(x0,x1,15); tf_r(x0,x1,26); tf_r(x0,x1,6);
    x0 += k0; x1 += k1 + 3u;
    tf_r(x0,x1,17); tf_r(x0,x1,29); tf_r(x0,x1,16); tf_r(x0,x1,24);
    x0 += k1; x1 += k2 + 4u;
    tf_r(x0,x1,13); tf_r(x0,x1,15); tf_r(x0,x1,26); tf_r(x0,x1,6);
    x0 += k2; x1 += k0 + 5u;
    return make_uint2(x0, x1);
}

__device__ __forceinline__ float uniform_at(uint32_t k0, uint32_t k1, uint32_t idx) {
    uint2 r = threefry2x32(k0, k1, 0u, idx);
    uint32_t bits = r.x ^ r.y;
    const float TINY = 1.17549435e-38f;
    float f = __uint_as_float(0x3F800000u | (bits >> 9)) - 1.0f;
    return fmaxf(TINY, __fadd_rn(f, TINY));
}

// exact (reference-matching) gumbel
__device__ __forceinline__ float gumbel_exact(uint32_t k0, uint32_t k1, uint32_t idx) {
    float u = uniform_at(k0, k1, idx);
    return -logf(-logf(u));
}

// cheap gumbel: |g_cheap - g_exact| <= ~4.5e-5, branchless
__device__ __forceinline__ float gumbel_cheap(uint32_t k0, uint32_t k1, uint32_t idx) {
    float u = uniform_at(k0, k1, idx);
    float inner_m = -0.69314718056f * __log2f(u);
    float s = 1.0f - u;                                   // exact for u > 0.5
    float inner_s = s * fmaf(s, fmaf(s, 0.33333333f, 0.5f), 1.0f);
    float inner = (u > 0.99609375f) ? inner_s : inner_m;  // 1 - 2^-8 cutoff
    return -0.69314718056f * __log2f(inner);
}

// ---------------- the single fused kernel ----------------
__global__ __launch_bounds__(256, 2) void k_main(const float* __restrict__ x,
                                                 const float* __restrict__ ws,
                                                 const float* __restrict__ wc,
                                                 float* __restrict__ out) {
    extern __shared__ __align__(16) char smem_raw[];
    float* sXs = (float*)smem_raw;            // 64*68
    float* sXc = sXs + 64 * XP;               // 64*68
    float* sW  = sXc + 64 * XP;               // 128*68
    float* sWc = sW  + 128 * XP;              // 16*68
    float* sWW = sWc + 16 * XP;               // 128
    float* sWWc = sWW + 128;                  // 16
    float* sXN = sWWc + 16;                   // 64
    float* sCN = sXN + 64;                    // 64
    int*   sBG = (int*)(sCN + 64);            // 64
    int*   sSI = sBG + 64;                    // 64
    int*   sCI = sSI + 64;                    // 64
    uint32_t* sKey = (uint32_t*)(sCI + 64);   // 4
    float* sLossW = (float*)(sKey + 4);       // 8
    int*   sVC = (int*)(sLossW + 8);          // 1
    int*   sFG = sVC + 1;                     // 1

    __shared__ double sdd[256];
    __shared__ int isLast;

    int tid = threadIdx.x, lane = tid & 31, w = tid >> 5;
    int ci = tid & 15, ri = tid >> 4;
    int rowbase = blockIdx.x * RPB;

    if (tid == 0) {
        uint2 a = threefry2x32(0u, 42u, 0u, 0u);   // ks
        uint2 b = threefry2x32(0u, 42u, 0u, 1u);   // kc
        sKey[0] = a.x; sKey[1] = a.y; sKey[2] = b.x; sKey[3] = b.y;
        *sVC = 0; *sFG = 0;
    }

    // load X tile: 64 rows x 128 -> split halves into padded smem
    const float4* gx = (const float4*)(x + (size_t)rowbase * CD);
    #pragma unroll
    for (int i = tid; i < RPB * 32; i += 256) {
        float4 v = gx[i];
        int r = i >> 5, c4 = i & 31;
        if (c4 < 16) ((float4*)(sXs + r * XP))[c4] = v;
        else         ((float4*)(sXc + r * XP))[c4 - 16] = v;
    }
    // color codebook + norms (16 lanes per code row reduce their dot4s)
    {
        float4 v = ((const float4*)wc)[tid];
        ((float4*)(sWc + (tid >> 4) * XP))[tid & 15] = v;
        float pd = __fadd_rn(__fadd_rn(__fmul_rn(v.x, v.x), __fmul_rn(v.y, v.y)),
                             __fadd_rn(__fmul_rn(v.z, v.z), __fmul_rn(v.w, v.w)));
        #pragma unroll
        for (int o = 8; o > 0; o >>= 1)
            pd = __fadd_rn(pd, __shfl_xor_sync(0xffffffffu, pd, o));
        if ((tid & 15) == 0) sWWc[tid >> 4] = pd;
    }
    __syncthreads();

    // per-row bg + half-norms: warp w -> rows w*8..+7, 4 lanes per row
    {
        int r = w * 8 + (lane >> 2);
        int part = lane & 3;
        float sa = 0.f, ss = 0.f, sc = 0.f;
        #pragma unroll
        for (int j = 0; j < 16; j++) {
            float a = sXs[r * XP + part * 16 + j];
            float b = sXc[r * XP + part * 16 + j];
            sa += fabsf(a) + fabsf(b);
            ss = __fmaf_rn(a, a, ss);
            sc = __fmaf_rn(b, b, sc);
        }
        #pragma unroll
        for (int o = 1; o < 4; o <<= 1) {
            sa += __shfl_xor_sync(0xffffffffu, sa, o);
            ss += __shfl_xor_sync(0xffffffffu, ss, o);
            sc += __shfl_xor_sync(0xffffffffu, sc, o);
        }
        if (part == 0) {
            int b = (sa < 1e-6f);
            sBG[r] = b; sXN[r] = ss; sCN[r] = sc;
            if (!b) *sFG = 1;
        }
    }
    __syncthreads();
    int anyfg = *sFG;
    uint32_t ks0 = sKey[0], ks1 = sKey[1], kc0 = sKey[2], kc1 = sKey[3];

    // per-row cheap top-2 screening state (per q)
    float v1[4], v2[4], lg1[4], lg2v[4];
    int   c1[4], c2[4];
    #pragma unroll
    for (int q = 0; q < 4; q++) {
        v1[q] = -INFINITY; v2[q] = -INFINITY;
        c1[q] = 0; c2[q] = 0; lg1[q] = 0.f; lg2v[q] = 0.f;
    }

    int ntile = anyfg ? 4 : 1;
    for (int tile = 0; tile < ntile; ++tile) {
        // load W tile + compute code norms in-flight
        {
            const float4* gw = (const float4*)(ws + (size_t)tile * 128 * HD);
            #pragma unroll
            for (int i = tid; i < 128 * 16; i += 256) {
                float4 v = gw[i];
                ((float4*)(sW + (i >> 4) * XP))[i & 15] = v;
                float pd = __fadd_rn(__fadd_rn(__fmul_rn(v.x, v.x), __fmul_rn(v.y, v.y)),
                                     __fadd_rn(__fmul_rn(v.z, v.z), __fmul_rn(v.w, v.w)));
                #pragma unroll
                for (int o = 8; o > 0; o >>= 1)
                    pd = __fadd_rn(pd, __shfl_xor_sync(0xffffffffu, pd, o));
                if ((tid & 15) == 0) sWW[i >> 4] = pd;
            }
        }
        __syncthreads();

        // packed f32x2 accumulators: lo = even-k partial, hi = odd-k partial
        unsigned long long acc[4][8];
        #pragma unroll
        for (int q = 0; q < 4; q++)
            #pragma unroll
            for (int m = 0; m < 8; m++) acc[q][m] = 0ull;

        if (anyfg) {
            #pragma unroll
            for (int k4 = 0; k4 < 16; k4++) {
                ulonglong2 xv[4];
                #pragma unroll
                for (int q = 0; q < 4; q++)
                    xv[q] = ((const ulonglong2*)(sXs + (16 * q + ri) * XP))[k4];
                #pragma unroll
                for (int m = 0; m < 8; m++) {
                    ulonglong2 wv = ((const ulonglong2*)(sW + (ci + 16 * m) * XP))[k4];
                    #pragma unroll
                    for (int q = 0; q < 4; q++) {
                        acc[q][m] = ffma2(xv[q].x, wv.x, acc[q][m]);
                        acc[q][m] = ffma2(xv[q].y, wv.y, acc[q][m]);
                    }
                }
            }
        }

        // cheap-screened candidate evaluation -> per-thread top-2
        #pragma unroll
        for (int q = 0; q < 4; q++) {
            int r = 16 * q + ri;
            int bg = sBG[r];
            float xs = sXN[r];
            uint32_t rowoff = (uint32_t)(rowbase + r) << 9;  // *512
            #pragma unroll
            for (int m = 0; m < 8; m++) {
                int code = tile * 128 + ci + 16 * m;
                bool allowed = bg ? (code < KCO) : (code >= KCO);
                if (allowed) {
                    float a = fold2(acc[q][m]);
                    float d = __fadd_rn(__fadd_rn(xs, sWW[ci + 16 * m]),
                                        -__fmul_rn(2.f, a));
                    float lg = -d;                        // exact logit
                    float g = gumbel_cheap(ks0, ks1, rowoff + (uint32_t)code);
                    float v = __fadd_rn(lg, g);
                    if (v > v1[q]) {
                        v2[q] = v1[q]; c2[q] = c1[q]; lg2v[q] = lg1[q];
                        v1[q] = v; c1[q] = code; lg1[q] = lg;
                    } else if (v > v2[q]) {
                        v2[q] = v; c2[q] = code; lg2v[q] = lg;
                    }
                }
            }
        }
        __syncthreads();  // before sW/sWW overwrite next tile
    }

    // ---- color: thread handles code ci for its 4 rows (exact path) ----
    float cbest[4]; int cbidx[4];
    #pragma unroll
    for (int q = 0; q < 4; q++) {
        int r = 16 * q + ri;
        unsigned long long a2 = 0ull;
        #pragma unroll
        for (int k4 = 0; k4 < 16; k4++) {
            ulonglong2 xv = ((const ulonglong2*)(sXc + r * XP))[k4];
            ulonglong2 wv = ((const ulonglong2*)(sWc + ci * XP))[k4];
            a2 = ffma2(xv.x, wv.x, a2);
            a2 = ffma2(xv.y, wv.y, a2);
        }
        float a = fold2(a2);
        float g = gumbel_exact(kc0, kc1, ((uint32_t)(rowbase + r) << 4) + (uint32_t)ci);
        float d = __fadd_rn(__fadd_rn(sCN[r], sWWc[ci]), -__fmul_rn(2.f, a));
        cbest[q] = __fadd_rn(-d, g);
        cbidx[q] = ci;
    }

    // ---- cross-lane reductions over the 16 ci lanes ----
    #pragma unroll
    for (int o = 8; o > 0; o >>= 1) {
        #pragma unroll
        for (int q = 0; q < 4; q++) {
            // top-2 merge for shape
            float ov1 = __shfl_xor_sync(0xffffffffu, v1[q], o);
            int   oc1 = __shfl_xor_sync(0xffffffffu, c1[q], o);
            float ol1 = __shfl_xor_sync(0xffffffffu, lg1[q], o);
            float ov2 = __shfl_xor_sync(0xffffffffu, v2[q], o);
            int   oc2 = __shfl_xor_sync(0xffffffffu, c2[q], o);
            float ol2 = __shfl_xor_sync(0xffffffffu, lg2v[q], o);
            bool takeO = (ov1 > v1[q]) || (ov1 == v1[q] && oc1 < c1[q]);
            float nv1 = takeO ? ov1 : v1[q];
            int   nc1 = takeO ? oc1 : c1[q];
            float nl1 = takeO ? ol1 : lg1[q];
            // loser of slot-1 contest:
            float lv = takeO ? v1[q] : ov1;
            int   lc = takeO ? c1[q] : oc1;
            float ll = takeO ? lg1[q] : ol1;
            // slot 2 = best of {loser, v2, ov2}
            float nv2 = lv; int nc2 = lc; float nl2 = ll;
            if (v2[q] > nv2 || (v2[q] == nv2 && c2[q] < nc2)) { nv2 = v2[q]; nc2 = c2[q]; nl2 = lg2v[q]; }
            if (ov2  > nv2 || (ov2  == nv2 && oc2  < nc2)) { nv2 = ov2;  nc2 = oc2;  nl2 = ol2; }
            v1[q] = nv1; c1[q] = nc1; lg1[q] = nl1;
            v2[q] = nv2; c2[q] = nc2; lg2v[q] = nl2;
            // color argmax
            float cv = __shfl_xor_sync(0xffffffffu, cbest[q], o);
            int   cb = __shfl_xor_sync(0xffffffffu, cbidx[q], o);
            if (cv > cbest[q] || (cv == cbest[q] && cb < cbidx[q])) { cbest[q] = cv; cbidx[q] = cb; }
        }
    }
    if ((lane & 15) == 0) {
        #pragma unroll
        for (int q = 0; q < 4; q++) {
            int r = 16 * q + ri;
            int widx;
            if (v1[q] - v2[q] > GAP) {
                widx = c1[q];                         // certain winner
            } else {
                // rare (~1e-4/row): exact tie-break between the two finalists
                uint32_t rowoff = (uint32_t)(rowbase + r) << 9;
                float e1 = __fadd_rn(lg1[q], gumbel_exact(ks0, ks1, rowoff + (uint32_t)c1[q]));
                float e2 = __fadd_rn(lg2v[q], gumbel_exact(ks0, ks1, rowoff + (uint32_t)c2[q]));
                widx = (e2 > e1 || (e2 == e1 && c2[q] < c1[q])) ? c2[q] : c1[q];
            }
            sSI[r] = widx;
            sCI[r] = cbidx[q];
        }
    }
    __syncthreads();

    // ---- outputs: quantized rows, idx, usage, loss ----
    float eacc = 0.f; int vcnt = 0;
    for (int t = 0; t < 8; t++) {
        int r = w * 8 + t;
        int widx = sSI[r], cidx = sCI[r];
        size_t grow = (size_t)rowbase + r;
        float4 wv, xv;
        if (lane < 16) {
            wv = ((const float4*)(ws + widx * HD))[lane];
            xv = ((const float4*)(sXs + r * XP))[lane];
        } else {
            wv = ((const float4*)(wc + cidx * HD))[lane - 16];
            xv = ((const float4*)(sXc + r * XP))[lane - 16];
        }
        ((float4*)out)[grow * 32 + lane] = wv;
        float dx = wv.x - xv.x, dy = wv.y - xv.y, dz = wv.z - xv.z, dw = wv.w - xv.w;
        float e = dx * dx + dy * dy + dz * dz + dw * dw;
        #pragma unroll
        for (int o = 16; o > 0; o >>= 1)
            e += __shfl_xor_sync(0xffffffffu, e, o);
        if (lane == 0) {
            out[IDX_OFF + grow] = (float)widx;
            if (!sBG[r]) {
                atomicAdd(&g_usage_s[widx], 1);
                atomicAdd(&g_usage_c[cidx], 1);
                vcnt++;
                eacc += e;
            }
        }
    }
    if (lane == 0) {
        sLossW[w] = eacc;
        atomicAdd(sVC, vcnt);
    }
    __syncthreads();
    if (tid == 0) {
        double L = 0.0;
        #pragma unroll
        for (int i = 0; i < 8; i++) L += (double)sLossW[i];
        g_loss_part[blockIdx.x] = L;
        atomicAdd(&g_vcount, *sVC);
    }

    // ---- last block finalizes + resets accumulators (graph-replay safe) ----
    __threadfence();
    if (tid == 0) {
        int t = atomicAdd(&g_ticket, 1);
        isLast = (t == NBLK - 1);
    }
    __syncthreads();
    if (!isLast) return;
    __threadfence();

    double a = 0.0;
    for (int i = tid; i < NBLK; i += 256) a += g_loss_part[i];
    sdd[tid] = a; __syncthreads();
    for (int s = 128; s > 0; s >>= 1) { if (tid < s) sdd[tid] += sdd[tid + s]; __syncthreads(); }
    double vc = (double)g_vcount;
    if (tid == 0) out[LOSS_OFF] = (float)(1.25 * sdd[0] / (vc * 128.0));
    __syncthreads();

    double e = 0.0;
    for (int i = tid; i < KSH; i += 256) {
        double p = (double)g_usage_s[i] / vc;
        e += p * log(p + 1e-10);
        out[US_OFF + i] = (float)g_usage_s[i];
    }
    sdd[tid] = e; __syncthreads();
    for (int s = 128; s > 0; s >>= 1) { if (tid < s) sdd[tid] += sdd[tid + s]; __syncthreads(); }
    if (tid == 0) out[PS_OFF] = (float)exp(-sdd[0]);
    __syncthreads();

    double ec = 0.0;
    if (tid < KCO) {
        double p = (double)g_usage_c[tid] / vc;
        ec = p * log(p + 1e-10);
        out[UC_OFF + tid] = (float)g_usage_c[tid];
    }
    sdd[tid] = ec; __syncthreads();
    for (int s = 128; s > 0; s >>= 1) { if (tid < s) sdd[tid] += sdd[tid + s]; __syncthreads(); }
    if (tid == 0) out[PC_OFF] = (float)exp(-sdd[0]);
    __syncthreads();

    // reset for next launch/replay
    for (int i = tid; i < KSH; i += 256) g_usage_s[i] = 0;
    if (tid < KCO) g_usage_c[tid] = 0;
    if (tid == 0) { g_vcount = 0; g_ticket = 0; }
}

#define SMEM_BYTES ((64*XP + 64*XP + 128*XP + 16*XP + 128 + 16 + 64 + 64) * 4 \
                    + (64 + 64 + 64 + 4 + 8 + 1 + 1) * 4 + 64)

extern "C" void kernel_launch(void* const* d_in, const int* in_sizes, int n_in,
                              void* d_out, int out_size) {
    const float* x  = (const float*)d_in[0];   // inputs [16,4096,128]
    const float* ws = (const float*)d_in[2];   // w_shape [512,64]
    const float* wc = (const float*)d_in[3];   // w_color [16,64]
    float* out = (float*)d_out;
    cudaFuncSetAttribute(k_main, cudaFuncAttributeMaxDynamicSharedMemorySize, SMEM_BYTES);
    k_main<<<NBLK, 256, SMEM_BYTES>>>(x, ws, wc, out);
}